// round 11
// baseline (speedup 1.0000x reference)
#include <cuda_runtime.h>

// Relativistic charged-particle Lagrangian dynamics — single fused kernel,
// ILP=2: each thread processes two independent rows so ptxas can interleave
// the two long dependency chains (ds-det, xla_tanh) that leave schedulers
// idle 38% of cycles at ILP=1. Arithmetic is bit-identical to the best
// previous kernel (R8): bit-exact XLA H (tanh rational approx, fma k-chains,
// (0.1*A_j)*A_i association, const-folded +eta), Cramer solve with accurate
// 2x2 minors + double-single det, routing at 4*RCOND to a cold fp64
// adjugate/deflation path (recomputes from y, keeping the hot path lean).

#define RCOND 4.7683716e-6f   /* 10 * 4 * eps(f32): jnp pinv default */

__constant__ float c_W[16];
__constant__ float c_V[16];

// ---------- XLA GPU f32 tanh ----------
__device__ __forceinline__ float xla_tanh(float x) {
    float ax = fabsf(x);
    float xc = fminf(fmaxf(x, -7.90531110763549805f), 7.90531110763549805f);
    float x2 = __fmul_rn(xc, xc);
    float np = -2.76076847742355e-16f;
    np = __fmaf_rn(np, x2, 2.00018790482477e-13f);
    np = __fmaf_rn(np, x2, -8.60467152213735e-11f);
    np = __fmaf_rn(np, x2, 5.12229709037114e-08f);
    np = __fmaf_rn(np, x2, 1.48572235717979e-05f);
    np = __fmaf_rn(np, x2, 6.37261928875436e-04f);
    np = __fmaf_rn(np, x2, 4.89352455891786e-03f);
    float num = __fmul_rn(xc, np);
    float dp = 1.19825839466702e-06f;
    dp = __fmaf_rn(dp, x2, 1.18534705686654e-04f);
    dp = __fmaf_rn(dp, x2, 2.26843463243900e-03f);
    dp = __fmaf_rn(dp, x2, 4.89352518554385e-03f);
    float r = __fdiv_rn(num, dp);
    return (ax < 0.0004f) ? x : r;
}

// ---------- double-single helpers ----------
__device__ __forceinline__ void two_sum(float a, float b, float& s, float& e) {
    s = a + b;
    float bb = s - a;
    e = (a - (s - bb)) + (b - bb);
}
__device__ __forceinline__ void two_prod(float a, float b, float& p, float& e) {
    p = a * b;
    e = fmaf(a, b, -p);
}
__device__ __forceinline__ float dif2(float p0, float p1, float q0, float q1) {
    float w = q0 * q1;
    float e = fmaf(q0, q1, -w);
    float r = fmaf(p0, p1, -w);
    return r - e;
}

// ---------- physics: J_uu (bit-exact vs reference) + force (compact) ----------
__device__ __forceinline__ void compute_mf(const float4* __restrict__ y,
                                           int b, float m[4][4], float force[4])
{
    const float eta[4] = {1.f, -1.f, -1.f, -1.f};
    float4 xv = y[2 * b];
    float4 uv = y[2 * b + 1];
    float x[4] = {xv.x, xv.y, xv.z, xv.w};
    float u[4] = {uv.x, uv.y, uv.z, uv.w};

    float A[4], dk[4];
#pragma unroll
    for (int i = 0; i < 4; i++) {
        float wx = __fmul_rn(c_W[i*4+0], x[0]);
        wx = __fmaf_rn(c_W[i*4+1], x[1], wx);
        wx = __fmaf_rn(c_W[i*4+2], x[2], wx);
        wx = __fmaf_rn(c_W[i*4+3], x[3], wx);
        float vx = __fmul_rn(c_V[i*4+0], x[0]);
        vx = __fmaf_rn(c_V[i*4+1], x[1], vx);
        vx = __fmaf_rn(c_V[i*4+2], x[2], vx);
        vx = __fmaf_rn(c_V[i*4+3], x[3], vx);
        float t = xla_tanh(wx);
        A[i]  = __fadd_rn(t, vx);
        dk[i] = __fsub_rn(1.0f, __fmul_rn(t, t));
    }

    // ---- J_uu: BIT-CRITICAL layout (matches reference autodiff graph) ----
    float oA[4];
#pragma unroll
    for (int j = 0; j < 4; j++)
        oA[j] = __fmul_rn(0.1f, A[j]);
#pragma unroll
    for (int i = 0; i < 4; i++) {
#pragma unroll
        for (int j = 0; j < 4; j++)
            m[i][j] = __fmul_rn(oA[j], A[i]);
        float xx2 = __fmul_rn(__fmul_rn(0.2f, x[i]), x[i]);
        m[i][i] = __fadd_rn(__fadd_rn(m[i][i], xx2), eta[i]);
    }

    // ---- force: compact algebra (rounding not kappa-amplified) ----
    float G[4][4];
#pragma unroll
    for (int k = 0; k < 4; k++)
#pragma unroll
        for (int j = 0; j < 4; j++)
            G[j][k] = fmaf(c_W[k*4+j], dk[k], c_V[k*4+j]);

    float s = u[0]*A[0] + u[1]*A[1] + u[2]*A[2] + u[3]*A[3];
    float tbs = 0.1f * s;

    float g[4], ge[4], h[4];
#pragma unroll
    for (int j = 0; j < 4; j++) {
        g[j]  = G[j][0]*u[0] + G[j][1]*u[1] + G[j][2]*u[2] + G[j][3]*u[3];
        ge[j] = G[j][0]*u[0] - G[j][1]*u[1] - G[j][2]*u[2] - G[j][3]*u[3];
        h[j]  = G[0][j]*u[0] + G[1][j]*u[1] + G[2][j]*u[2] + G[3][j]*u[3];
    }
    float p = h[0]*u[0] + h[1]*u[1] + h[2]*u[2] + h[3]*u[3];

#pragma unroll
    for (int j = 0; j < 4; j++) {
        force[j] = -0.2f * x[j] * u[j] * u[j]
                 + 0.5f * ge[j] + tbs * g[j]
                 - 0.5f * eta[j] * h[j] - tbs * h[j]
                 - 0.1f * p * A[j];
    }
}

// ---------- cold path: bit-exact recompute + fp64 pinv (no fp64 div/sqrt) ----
__device__ __noinline__ float4 solve_slow(const float4* __restrict__ y, int b)
{
    float mm[4][4], ff[4];
    compute_mf(y, b, mm, ff);

    double M[4][4], F[4];
#pragma unroll
    for (int i = 0; i < 4; i++) {
        F[i] = (double)ff[i];
#pragma unroll
        for (int j = 0; j < 4; j++)
            M[i][j] = (double)mm[i][j];
    }

    double s0 = M[0][0]*M[1][1] - M[1][0]*M[0][1];
    double s1 = M[0][0]*M[1][2] - M[1][0]*M[0][2];
    double s2 = M[0][0]*M[1][3] - M[1][0]*M[0][3];
    double s3 = M[0][1]*M[1][2] - M[1][1]*M[0][2];
    double s4 = M[0][1]*M[1][3] - M[1][1]*M[0][3];
    double s5 = M[0][2]*M[1][3] - M[1][2]*M[0][3];
    double c5 = M[2][2]*M[3][3] - M[3][2]*M[2][3];
    double c4 = M[2][1]*M[3][3] - M[3][1]*M[2][3];
    double c3 = M[2][1]*M[3][2] - M[3][1]*M[2][2];
    double c2 = M[2][0]*M[3][3] - M[3][0]*M[2][3];
    double c1 = M[2][0]*M[3][2] - M[3][0]*M[2][2];
    double c0 = M[2][0]*M[3][1] - M[3][0]*M[2][1];

    double det = s0*c5 - s1*c4 + s2*c3 + s3*c2 - s4*c1 + s5*c0;

    double adj[4][4];
    adj[0][0] =  M[1][1]*c5 - M[1][2]*c4 + M[1][3]*c3;
    adj[0][1] = -M[0][1]*c5 + M[0][2]*c4 - M[0][3]*c3;
    adj[0][2] =  M[3][1]*s5 - M[3][2]*s4 + M[3][3]*s3;
    adj[0][3] = -M[2][1]*s5 + M[2][2]*s4 - M[2][3]*s3;
    adj[1][0] = -M[1][0]*c5 + M[1][2]*c2 - M[1][3]*c1;
    adj[1][1] =  M[0][0]*c5 - M[0][2]*c2 + M[0][3]*c1;
    adj[1][2] = -M[3][0]*s5 + M[3][2]*s2 - M[3][3]*s1;
    adj[1][3] =  M[2][0]*s5 - M[2][2]*s2 + M[2][3]*s1;
    adj[2][0] =  M[1][0]*c4 - M[1][1]*c2 + M[1][3]*c0;
    adj[2][1] = -M[0][0]*c4 + M[0][1]*c2 - M[0][3]*c0;
    adj[2][2] =  M[3][0]*s4 - M[3][1]*s2 + M[3][3]*s0;
    adj[2][3] = -M[2][0]*s4 + M[2][1]*s2 - M[2][3]*s0;
    adj[3][0] = -M[1][0]*c3 + M[1][1]*c1 - M[1][2]*c0;
    adj[3][1] =  M[0][0]*c3 - M[0][1]*c1 + M[0][2]*c0;
    adj[3][2] = -M[3][0]*s3 + M[3][1]*s1 - M[3][2]*s0;
    adj[3][3] =  M[2][0]*s3 - M[2][1]*s1 + M[2][2]*s0;

    double rdet = (double)__frcp_rn((float)det);
    rdet = rdet * (2.0 - det * rdet);
    rdet = rdet * (2.0 - det * rdet);

    double acc[4];
#pragma unroll
    for (int j = 0; j < 4; j++)
        acc[j] = (F[0]*adj[0][j] + F[1]*adj[1][j]
                + F[2]*adj[2][j] + F[3]*adj[3][j]) * rdet;

    // null direction: dominant adjugate column + one refinement multiply
    double cn[4];
#pragma unroll
    for (int c = 0; c < 4; c++)
        cn[c] = adj[0][c]*adj[0][c] + adj[1][c]*adj[1][c]
              + adj[2][c]*adj[2][c] + adj[3][c]*adj[3][c];
    int cbest = 0;
    if (cn[1] > cn[cbest]) cbest = 1;
    if (cn[2] > cn[cbest]) cbest = 2;
    if (cn[3] > cn[cbest]) cbest = 3;
    double v[4] = {adj[0][cbest], adj[1][cbest], adj[2][cbest], adj[3][cbest]};
    double v2[4];
#pragma unroll
    for (int i = 0; i < 4; i++)
        v2[i] = adj[i][0]*v[0] + adj[i][1]*v[1] + adj[i][2]*v[2] + adj[i][3]*v[3];

    double Mv[4];
#pragma unroll
    for (int i = 0; i < 4; i++)
        Mv[i] = M[i][0]*v2[0] + M[i][1]*v2[1] + M[i][2]*v2[2] + M[i][3]*v2[3];
    double num = v2[0]*Mv[0] + v2[1]*Mv[1] + v2[2]*Mv[2] + v2[3]*Mv[3];
    double den = v2[0]*v2[0] + v2[1]*v2[1] + v2[2]*v2[2] + v2[3]*v2[3];

    // sigma_max^2 via power iteration on M^2 (compare in squares, no sqrt)
    double tn[4];
#pragma unroll
    for (int c = 0; c < 4; c++)
        tn[c] = M[0][c]*M[0][c] + M[1][c]*M[1][c]
              + M[2][c]*M[2][c] + M[3][c]*M[3][c];
    int tbest = 0;
    if (tn[1] > tn[tbest]) tbest = 1;
    if (tn[2] > tn[tbest]) tbest = 2;
    if (tn[3] > tn[tbest]) tbest = 3;
    double t[4] = {M[0][tbest], M[1][tbest], M[2][tbest], M[3][tbest]};
#pragma unroll
    for (int it = 0; it < 6; it++) {
        double tt0 = M[0][0]*t[0] + M[0][1]*t[1] + M[0][2]*t[2] + M[0][3]*t[3];
        double tt1 = M[1][0]*t[0] + M[1][1]*t[1] + M[1][2]*t[2] + M[1][3]*t[3];
        double tt2 = M[2][0]*t[0] + M[2][1]*t[1] + M[2][2]*t[2] + M[2][3]*t[3];
        double tt3 = M[3][0]*t[0] + M[3][1]*t[1] + M[3][2]*t[2] + M[3][3]*t[3];
        t[0] = tt0; t[1] = tt1; t[2] = tt2; t[3] = tt3;
    }
    double z0 = M[0][0]*t[0] + M[0][1]*t[1] + M[0][2]*t[2] + M[0][3]*t[3];
    double z1 = M[1][0]*t[0] + M[1][1]*t[1] + M[1][2]*t[2] + M[1][3]*t[3];
    double z2 = M[2][0]*t[0] + M[2][1]*t[1] + M[2][2]*t[2] + M[2][3]*t[3];
    double z3 = M[3][0]*t[0] + M[3][1]*t[1] + M[3][2]*t[2] + M[3][3]*t[3];
    double zz = z0*z0 + z1*z1 + z2*z2 + z3*z3;
    double tt = t[0]*t[0] + t[1]*t[1] + t[2]*t[2] + t[3]*t[3];
    double R2 = (double)RCOND * (double)RCOND;
    bool keep = (num*num)*tt > R2*zz*(den*den);

    if (!keep) {
        double rden = (double)__frcp_rn((float)den);
        rden = rden * (2.0 - den * rden);
        rden = rden * (2.0 - den * rden);
        double proj = (v2[0]*acc[0] + v2[1]*acc[1]
                     + v2[2]*acc[2] + v2[3]*acc[3]) * rden;
#pragma unroll
        for (int j = 0; j < 4; j++)
            acc[j] -= proj * v2[j];
    }

    return make_float4((float)acc[0], (float)acc[1], (float)acc[2], (float)acc[3]);
}

// ---------- hot row: branch-free fast solve + routing flag ----------
__device__ __forceinline__ float4 row_fast(const float4* __restrict__ y,
                                           int b, bool& routed)
{
    float m[4][4], f[4];
    compute_mf(y, b, m, f);

    float s0 = dif2(m[0][0], m[1][1], m[1][0], m[0][1]);
    float s1 = dif2(m[0][0], m[1][2], m[1][0], m[0][2]);
    float s2 = dif2(m[0][0], m[1][3], m[1][0], m[0][3]);
    float s3 = dif2(m[0][1], m[1][2], m[1][1], m[0][2]);
    float s4 = dif2(m[0][1], m[1][3], m[1][1], m[0][3]);
    float s5 = dif2(m[0][2], m[1][3], m[1][2], m[0][3]);

    float c5 = dif2(m[2][2], m[3][3], m[3][2], m[2][3]);
    float c4 = dif2(m[2][1], m[3][3], m[3][1], m[2][3]);
    float c3 = dif2(m[2][1], m[3][2], m[3][1], m[2][2]);
    float c2 = dif2(m[2][0], m[3][3], m[3][0], m[2][3]);
    float c1 = dif2(m[2][0], m[3][2], m[3][0], m[2][2]);
    float c0 = dif2(m[2][0], m[3][1], m[3][0], m[2][1]);

    float hi, lo, p, e, t;
    two_prod(s0, c5, hi, lo);
    two_prod(-s1, c4, p, e); two_sum(hi, p, hi, t); lo += t + e;
    two_prod(s2, c3, p, e);  two_sum(hi, p, hi, t); lo += t + e;
    two_prod(s3, c2, p, e);  two_sum(hi, p, hi, t); lo += t + e;
    two_prod(-s4, c1, p, e); two_sum(hi, p, hi, t); lo += t + e;
    two_prod(s5, c0, p, e);  two_sum(hi, p, hi, t); lo += t + e;

    float adj[4][4];
    adj[0][0] =  m[1][1]*c5 - m[1][2]*c4 + m[1][3]*c3;
    adj[0][1] = -m[0][1]*c5 + m[0][2]*c4 - m[0][3]*c3;
    adj[0][2] =  m[3][1]*s5 - m[3][2]*s4 + m[3][3]*s3;
    adj[0][3] = -m[2][1]*s5 + m[2][2]*s4 - m[2][3]*s3;
    adj[1][0] = -m[1][0]*c5 + m[1][2]*c2 - m[1][3]*c1;
    adj[1][1] =  m[0][0]*c5 - m[0][2]*c2 + m[0][3]*c1;
    adj[1][2] = -m[3][0]*s5 + m[3][2]*s2 - m[3][3]*s1;
    adj[1][3] =  m[2][0]*s5 - m[2][2]*s2 + m[2][3]*s1;
    adj[2][0] =  m[1][0]*c4 - m[1][1]*c2 + m[1][3]*c0;
    adj[2][1] = -m[0][0]*c4 + m[0][1]*c2 - m[0][3]*c0;
    adj[2][2] =  m[3][0]*s4 - m[3][1]*s2 + m[3][3]*s0;
    adj[2][3] = -m[2][0]*s4 + m[2][1]*s2 - m[2][3]*s0;
    adj[3][0] = -m[1][0]*c3 + m[1][1]*c1 - m[1][2]*c0;
    adj[3][1] =  m[0][0]*c3 - m[0][1]*c1 + m[0][2]*c0;
    adj[3][2] = -m[3][0]*s3 + m[3][1]*s1 - m[3][2]*s0;
    adj[3][3] =  m[2][0]*s3 - m[2][1]*s1 + m[2][2]*s0;

    // route iff det^2 < (4*RCOND)^2 * ||m||_F^2 * ||adj||_F^2
    float sF2 = 0.f, sAdj2 = 0.f;
#pragma unroll
    for (int i = 0; i < 4; i++)
#pragma unroll
        for (int j = 0; j < 4; j++) {
            sF2   = fmaf(m[i][j],   m[i][j],   sF2);
            sAdj2 = fmaf(adj[i][j], adj[i][j], sAdj2);
        }
    float det1 = hi + lo;
    const float CR = 4.0f * RCOND;
    routed = det1 * det1 < (CR * CR) * sF2 * sAdj2;

    float inv = 1.0f / hi;
    inv = fmaf(-lo, inv * inv, inv);   // 1/(hi+lo)

    float4 res;
    res.x = (f[0]*adj[0][0] + f[1]*adj[1][0] + f[2]*adj[2][0] + f[3]*adj[3][0]) * inv;
    res.y = (f[0]*adj[0][1] + f[1]*adj[1][1] + f[2]*adj[2][1] + f[3]*adj[3][1]) * inv;
    res.z = (f[0]*adj[0][2] + f[1]*adj[1][2] + f[2]*adj[2][2] + f[3]*adj[3][2]) * inv;
    res.w = (f[0]*adj[0][3] + f[1]*adj[1][3] + f[2]*adj[2][3] + f[3]*adj[3][3]) * inv;
    return res;
}

// ---------- the one kernel: 2 rows per thread ----------
__global__ void __launch_bounds__(256, 2)
rcpl_kernel(const float4* __restrict__ y,
            float4* __restrict__ out,
            int B)
{
    int tid = blockIdx.x * blockDim.x + threadIdx.x;
    int half = (B + 1) >> 1;
    if (tid >= half) return;

    int b0 = tid;
    int b1 = tid + half;

    // hot, branch-free compute for both rows in one basic block (ILP=2)
    bool r0 = false, r1 = false;
    float4 a0 = row_fast(y, b0, r0);
    float4 a1;
    bool have1 = b1 < B;
    if (have1) a1 = row_fast(y, b1, r1);

    // cold, rare fp64 pinv branches (recompute from y; bit-exact)
    if (r0) a0 = solve_slow(y, b0);
    if (have1 && r1) a1 = solve_slow(y, b1);

    out[b0] = a0;
    if (have1) out[b1] = a1;
}

extern "C" void kernel_launch(void* const* d_in, const int* in_sizes, int n_in,
                              void* d_out, int out_size)
{
    const float* y = (const float*)d_in[0];
    int B = in_sizes[0] / 8;   // y is [B, 8]

    cudaMemcpyToSymbolAsync(c_W, d_in[1], 16 * sizeof(float), 0,
                            cudaMemcpyDeviceToDevice, 0);
    cudaMemcpyToSymbolAsync(c_V, d_in[2], 16 * sizeof(float), 0,
                            cudaMemcpyDeviceToDevice, 0);

    int half = (B + 1) >> 1;
    int threads = 256;
    int blocks = (half + threads - 1) / threads;
    rcpl_kernel<<<blocks, threads>>>((const float4*)y, (float4*)d_out, B);
}

// round 12
// speedup vs baseline: 1.0889x; 1.0889x over previous
#include <cuda_runtime.h>

// Relativistic charged-particle Lagrangian dynamics — ONE graph node.
// R12 = R11 ILP=2 kernel (best kernel time: 21.4us) with W/V staged into
// shared memory from kernel args instead of __constant__ +
// cudaMemcpyToSymbolAsync (whose two graph nodes cost ~3.6us of replay
// overhead). Values are bit-identical; arithmetic unchanged:
//  - bit-exact XLA H (tanh rational approx, cublas fma k-chains,
//    (0.1*A_j)*A_i association, const-folded +eta)
//  - Cramer solve with accurate 2x2 minors + double-single det
//  - routing at 4*RCOND to a cold fp64 adjugate/deflation path
//    (no fp64 div/sqrt; recomputes from y)

#define RCOND 4.7683716e-6f   /* 10 * 4 * eps(f32): jnp pinv default */

// ---------- XLA GPU f32 tanh ----------
__device__ __forceinline__ float xla_tanh(float x) {
    float ax = fabsf(x);
    float xc = fminf(fmaxf(x, -7.90531110763549805f), 7.90531110763549805f);
    float x2 = __fmul_rn(xc, xc);
    float np = -2.76076847742355e-16f;
    np = __fmaf_rn(np, x2, 2.00018790482477e-13f);
    np = __fmaf_rn(np, x2, -8.60467152213735e-11f);
    np = __fmaf_rn(np, x2, 5.12229709037114e-08f);
    np = __fmaf_rn(np, x2, 1.48572235717979e-05f);
    np = __fmaf_rn(np, x2, 6.37261928875436e-04f);
    np = __fmaf_rn(np, x2, 4.89352455891786e-03f);
    float num = __fmul_rn(xc, np);
    float dp = 1.19825839466702e-06f;
    dp = __fmaf_rn(dp, x2, 1.18534705686654e-04f);
    dp = __fmaf_rn(dp, x2, 2.26843463243900e-03f);
    dp = __fmaf_rn(dp, x2, 4.89352518554385e-03f);
    float r = __fdiv_rn(num, dp);
    return (ax < 0.0004f) ? x : r;
}

// ---------- double-single helpers ----------
__device__ __forceinline__ void two_sum(float a, float b, float& s, float& e) {
    s = a + b;
    float bb = s - a;
    e = (a - (s - bb)) + (b - bb);
}
__device__ __forceinline__ void two_prod(float a, float b, float& p, float& e) {
    p = a * b;
    e = fmaf(a, b, -p);
}
__device__ __forceinline__ float dif2(float p0, float p1, float q0, float q1) {
    float w = q0 * q1;
    float e = fmaf(q0, q1, -w);
    float r = fmaf(p0, p1, -w);
    return r - e;
}

// ---------- physics: J_uu (bit-exact vs reference) + force (compact) ----------
__device__ __forceinline__ void compute_mf(const float4* __restrict__ y,
                                           const float* sW, const float* sV,
                                           int b, float m[4][4], float force[4])
{
    const float eta[4] = {1.f, -1.f, -1.f, -1.f};
    float4 xv = y[2 * b];
    float4 uv = y[2 * b + 1];
    float x[4] = {xv.x, xv.y, xv.z, xv.w};
    float u[4] = {uv.x, uv.y, uv.z, uv.w};

    float A[4], dk[4];
#pragma unroll
    for (int i = 0; i < 4; i++) {
        float wx = __fmul_rn(sW[i*4+0], x[0]);
        wx = __fmaf_rn(sW[i*4+1], x[1], wx);
        wx = __fmaf_rn(sW[i*4+2], x[2], wx);
        wx = __fmaf_rn(sW[i*4+3], x[3], wx);
        float vx = __fmul_rn(sV[i*4+0], x[0]);
        vx = __fmaf_rn(sV[i*4+1], x[1], vx);
        vx = __fmaf_rn(sV[i*4+2], x[2], vx);
        vx = __fmaf_rn(sV[i*4+3], x[3], vx);
        float t = xla_tanh(wx);
        A[i]  = __fadd_rn(t, vx);
        dk[i] = __fsub_rn(1.0f, __fmul_rn(t, t));
    }

    // ---- J_uu: BIT-CRITICAL layout (matches reference autodiff graph) ----
    float oA[4];
#pragma unroll
    for (int j = 0; j < 4; j++)
        oA[j] = __fmul_rn(0.1f, A[j]);
#pragma unroll
    for (int i = 0; i < 4; i++) {
#pragma unroll
        for (int j = 0; j < 4; j++)
            m[i][j] = __fmul_rn(oA[j], A[i]);
        float xx2 = __fmul_rn(__fmul_rn(0.2f, x[i]), x[i]);
        m[i][i] = __fadd_rn(__fadd_rn(m[i][i], xx2), eta[i]);
    }

    // ---- force: compact algebra (rounding not kappa-amplified) ----
    float G[4][4];
#pragma unroll
    for (int k = 0; k < 4; k++)
#pragma unroll
        for (int j = 0; j < 4; j++)
            G[j][k] = fmaf(sW[k*4+j], dk[k], sV[k*4+j]);

    float s = u[0]*A[0] + u[1]*A[1] + u[2]*A[2] + u[3]*A[3];
    float tbs = 0.1f * s;

    float g[4], ge[4], h[4];
#pragma unroll
    for (int j = 0; j < 4; j++) {
        g[j]  = G[j][0]*u[0] + G[j][1]*u[1] + G[j][2]*u[2] + G[j][3]*u[3];
        ge[j] = G[j][0]*u[0] - G[j][1]*u[1] - G[j][2]*u[2] - G[j][3]*u[3];
        h[j]  = G[0][j]*u[0] + G[1][j]*u[1] + G[2][j]*u[2] + G[3][j]*u[3];
    }
    float p = h[0]*u[0] + h[1]*u[1] + h[2]*u[2] + h[3]*u[3];

#pragma unroll
    for (int j = 0; j < 4; j++) {
        force[j] = -0.2f * x[j] * u[j] * u[j]
                 + 0.5f * ge[j] + tbs * g[j]
                 - 0.5f * eta[j] * h[j] - tbs * h[j]
                 - 0.1f * p * A[j];
    }
}

// ---------- cold path: bit-exact recompute + fp64 pinv (no fp64 div/sqrt) ----
__device__ __noinline__ float4 solve_slow(const float4* __restrict__ y,
                                          const float* sW, const float* sV, int b)
{
    float mm[4][4], ff[4];
    compute_mf(y, sW, sV, b, mm, ff);

    double M[4][4], F[4];
#pragma unroll
    for (int i = 0; i < 4; i++) {
        F[i] = (double)ff[i];
#pragma unroll
        for (int j = 0; j < 4; j++)
            M[i][j] = (double)mm[i][j];
    }

    double s0 = M[0][0]*M[1][1] - M[1][0]*M[0][1];
    double s1 = M[0][0]*M[1][2] - M[1][0]*M[0][2];
    double s2 = M[0][0]*M[1][3] - M[1][0]*M[0][3];
    double s3 = M[0][1]*M[1][2] - M[1][1]*M[0][2];
    double s4 = M[0][1]*M[1][3] - M[1][1]*M[0][3];
    double s5 = M[0][2]*M[1][3] - M[1][2]*M[0][3];
    double c5 = M[2][2]*M[3][3] - M[3][2]*M[2][3];
    double c4 = M[2][1]*M[3][3] - M[3][1]*M[2][3];
    double c3 = M[2][1]*M[3][2] - M[3][1]*M[2][2];
    double c2 = M[2][0]*M[3][3] - M[3][0]*M[2][3];
    double c1 = M[2][0]*M[3][2] - M[3][0]*M[2][2];
    double c0 = M[2][0]*M[3][1] - M[3][0]*M[2][1];

    double det = s0*c5 - s1*c4 + s2*c3 + s3*c2 - s4*c1 + s5*c0;

    double adj[4][4];
    adj[0][0] =  M[1][1]*c5 - M[1][2]*c4 + M[1][3]*c3;
    adj[0][1] = -M[0][1]*c5 + M[0][2]*c4 - M[0][3]*c3;
    adj[0][2] =  M[3][1]*s5 - M[3][2]*s4 + M[3][3]*s3;
    adj[0][3] = -M[2][1]*s5 + M[2][2]*s4 - M[2][3]*s3;
    adj[1][0] = -M[1][0]*c5 + M[1][2]*c2 - M[1][3]*c1;
    adj[1][1] =  M[0][0]*c5 - M[0][2]*c2 + M[0][3]*c1;
    adj[1][2] = -M[3][0]*s5 + M[3][2]*s2 - M[3][3]*s1;
    adj[1][3] =  M[2][0]*s5 - M[2][2]*s2 + M[2][3]*s1;
    adj[2][0] =  M[1][0]*c4 - M[1][1]*c2 + M[1][3]*c0;
    adj[2][1] = -M[0][0]*c4 + M[0][1]*c2 - M[0][3]*c0;
    adj[2][2] =  M[3][0]*s4 - M[3][1]*s2 + M[3][3]*s0;
    adj[2][3] = -M[2][0]*s4 + M[2][1]*s2 - M[2][3]*s0;
    adj[3][0] = -M[1][0]*c3 + M[1][1]*c1 - M[1][2]*c0;
    adj[3][1] =  M[0][0]*c3 - M[0][1]*c1 + M[0][2]*c0;
    adj[3][2] = -M[3][0]*s3 + M[3][1]*s1 - M[3][2]*s0;
    adj[3][3] =  M[2][0]*s3 - M[2][1]*s1 + M[2][2]*s0;

    double rdet = (double)__frcp_rn((float)det);
    rdet = rdet * (2.0 - det * rdet);
    rdet = rdet * (2.0 - det * rdet);

    double acc[4];
#pragma unroll
    for (int j = 0; j < 4; j++)
        acc[j] = (F[0]*adj[0][j] + F[1]*adj[1][j]
                + F[2]*adj[2][j] + F[3]*adj[3][j]) * rdet;

    // null direction: dominant adjugate column + one refinement multiply
    double cn[4];
#pragma unroll
    for (int c = 0; c < 4; c++)
        cn[c] = adj[0][c]*adj[0][c] + adj[1][c]*adj[1][c]
              + adj[2][c]*adj[2][c] + adj[3][c]*adj[3][c];
    int cbest = 0;
    if (cn[1] > cn[cbest]) cbest = 1;
    if (cn[2] > cn[cbest]) cbest = 2;
    if (cn[3] > cn[cbest]) cbest = 3;
    double v[4] = {adj[0][cbest], adj[1][cbest], adj[2][cbest], adj[3][cbest]};
    double v2[4];
#pragma unroll
    for (int i = 0; i < 4; i++)
        v2[i] = adj[i][0]*v[0] + adj[i][1]*v[1] + adj[i][2]*v[2] + adj[i][3]*v[3];

    double Mv[4];
#pragma unroll
    for (int i = 0; i < 4; i++)
        Mv[i] = M[i][0]*v2[0] + M[i][1]*v2[1] + M[i][2]*v2[2] + M[i][3]*v2[3];
    double num = v2[0]*Mv[0] + v2[1]*Mv[1] + v2[2]*Mv[2] + v2[3]*Mv[3];
    double den = v2[0]*v2[0] + v2[1]*v2[1] + v2[2]*v2[2] + v2[3]*v2[3];

    // sigma_max^2 via power iteration on M^2 (compare in squares, no sqrt)
    double tn[4];
#pragma unroll
    for (int c = 0; c < 4; c++)
        tn[c] = M[0][c]*M[0][c] + M[1][c]*M[1][c]
              + M[2][c]*M[2][c] + M[3][c]*M[3][c];
    int tbest = 0;
    if (tn[1] > tn[tbest]) tbest = 1;
    if (tn[2] > tn[tbest]) tbest = 2;
    if (tn[3] > tn[tbest]) tbest = 3;
    double t[4] = {M[0][tbest], M[1][tbest], M[2][tbest], M[3][tbest]};
#pragma unroll
    for (int it = 0; it < 6; it++) {
        double tt0 = M[0][0]*t[0] + M[0][1]*t[1] + M[0][2]*t[2] + M[0][3]*t[3];
        double tt1 = M[1][0]*t[0] + M[1][1]*t[1] + M[1][2]*t[2] + M[1][3]*t[3];
        double tt2 = M[2][0]*t[0] + M[2][1]*t[1] + M[2][2]*t[2] + M[2][3]*t[3];
        double tt3 = M[3][0]*t[0] + M[3][1]*t[1] + M[3][2]*t[2] + M[3][3]*t[3];
        t[0] = tt0; t[1] = tt1; t[2] = tt2; t[3] = tt3;
    }
    double z0 = M[0][0]*t[0] + M[0][1]*t[1] + M[0][2]*t[2] + M[0][3]*t[3];
    double z1 = M[1][0]*t[0] + M[1][1]*t[1] + M[1][2]*t[2] + M[1][3]*t[3];
    double z2 = M[2][0]*t[0] + M[2][1]*t[1] + M[2][2]*t[2] + M[2][3]*t[3];
    double z3 = M[3][0]*t[0] + M[3][1]*t[1] + M[3][2]*t[2] + M[3][3]*t[3];
    double zz = z0*z0 + z1*z1 + z2*z2 + z3*z3;
    double tt = t[0]*t[0] + t[1]*t[1] + t[2]*t[2] + t[3]*t[3];
    double R2 = (double)RCOND * (double)RCOND;
    bool keep = (num*num)*tt > R2*zz*(den*den);

    if (!keep) {
        double rden = (double)__frcp_rn((float)den);
        rden = rden * (2.0 - den * rden);
        rden = rden * (2.0 - den * rden);
        double proj = (v2[0]*acc[0] + v2[1]*acc[1]
                     + v2[2]*acc[2] + v2[3]*acc[3]) * rden;
#pragma unroll
        for (int j = 0; j < 4; j++)
            acc[j] -= proj * v2[j];
    }

    return make_float4((float)acc[0], (float)acc[1], (float)acc[2], (float)acc[3]);
}

// ---------- hot row: branch-free fast solve + routing flag ----------
__device__ __forceinline__ float4 row_fast(const float4* __restrict__ y,
                                           const float* sW, const float* sV,
                                           int b, bool& routed)
{
    float m[4][4], f[4];
    compute_mf(y, sW, sV, b, m, f);

    float s0 = dif2(m[0][0], m[1][1], m[1][0], m[0][1]);
    float s1 = dif2(m[0][0], m[1][2], m[1][0], m[0][2]);
    float s2 = dif2(m[0][0], m[1][3], m[1][0], m[0][3]);
    float s3 = dif2(m[0][1], m[1][2], m[1][1], m[0][2]);
    float s4 = dif2(m[0][1], m[1][3], m[1][1], m[0][3]);
    float s5 = dif2(m[0][2], m[1][3], m[1][2], m[0][3]);

    float c5 = dif2(m[2][2], m[3][3], m[3][2], m[2][3]);
    float c4 = dif2(m[2][1], m[3][3], m[3][1], m[2][3]);
    float c3 = dif2(m[2][1], m[3][2], m[3][1], m[2][2]);
    float c2 = dif2(m[2][0], m[3][3], m[3][0], m[2][3]);
    float c1 = dif2(m[2][0], m[3][2], m[3][0], m[2][2]);
    float c0 = dif2(m[2][0], m[3][1], m[3][0], m[2][1]);

    float hi, lo, p, e, t;
    two_prod(s0, c5, hi, lo);
    two_prod(-s1, c4, p, e); two_sum(hi, p, hi, t); lo += t + e;
    two_prod(s2, c3, p, e);  two_sum(hi, p, hi, t); lo += t + e;
    two_prod(s3, c2, p, e);  two_sum(hi, p, hi, t); lo += t + e;
    two_prod(-s4, c1, p, e); two_sum(hi, p, hi, t); lo += t + e;
    two_prod(s5, c0, p, e);  two_sum(hi, p, hi, t); lo += t + e;

    float adj[4][4];
    adj[0][0] =  m[1][1]*c5 - m[1][2]*c4 + m[1][3]*c3;
    adj[0][1] = -m[0][1]*c5 + m[0][2]*c4 - m[0][3]*c3;
    adj[0][2] =  m[3][1]*s5 - m[3][2]*s4 + m[3][3]*s3;
    adj[0][3] = -m[2][1]*s5 + m[2][2]*s4 - m[2][3]*s3;
    adj[1][0] = -m[1][0]*c5 + m[1][2]*c2 - m[1][3]*c1;
    adj[1][1] =  m[0][0]*c5 - m[0][2]*c2 + m[0][3]*c1;
    adj[1][2] = -m[3][0]*s5 + m[3][2]*s2 - m[3][3]*s1;
    adj[1][3] =  m[2][0]*s5 - m[2][2]*s2 + m[2][3]*s1;
    adj[2][0] =  m[1][0]*c4 - m[1][1]*c2 + m[1][3]*c0;
    adj[2][1] = -m[0][0]*c4 + m[0][1]*c2 - m[0][3]*c0;
    adj[2][2] =  m[3][0]*s4 - m[3][1]*s2 + m[3][3]*s0;
    adj[2][3] = -m[2][0]*s4 + m[2][1]*s2 - m[2][3]*s0;
    adj[3][0] = -m[1][0]*c3 + m[1][1]*c1 - m[1][2]*c0;
    adj[3][1] =  m[0][0]*c3 - m[0][1]*c1 + m[0][2]*c0;
    adj[3][2] = -m[3][0]*s3 + m[3][1]*s1 - m[3][2]*s0;
    adj[3][3] =  m[2][0]*s3 - m[2][1]*s1 + m[2][2]*s0;

    // route iff det^2 < (4*RCOND)^2 * ||m||_F^2 * ||adj||_F^2
    float sF2 = 0.f, sAdj2 = 0.f;
#pragma unroll
    for (int i = 0; i < 4; i++)
#pragma unroll
        for (int j = 0; j < 4; j++) {
            sF2   = fmaf(m[i][j],   m[i][j],   sF2);
            sAdj2 = fmaf(adj[i][j], adj[i][j], sAdj2);
        }
    float det1 = hi + lo;
    const float CR = 4.0f * RCOND;
    routed = det1 * det1 < (CR * CR) * sF2 * sAdj2;

    float inv = 1.0f / hi;
    inv = fmaf(-lo, inv * inv, inv);   // 1/(hi+lo)

    float4 res;
    res.x = (f[0]*adj[0][0] + f[1]*adj[1][0] + f[2]*adj[2][0] + f[3]*adj[3][0]) * inv;
    res.y = (f[0]*adj[0][1] + f[1]*adj[1][1] + f[2]*adj[2][1] + f[3]*adj[3][1]) * inv;
    res.z = (f[0]*adj[0][2] + f[1]*adj[1][2] + f[2]*adj[2][2] + f[3]*adj[3][2]) * inv;
    res.w = (f[0]*adj[0][3] + f[1]*adj[1][3] + f[2]*adj[2][3] + f[3]*adj[3][3]) * inv;
    return res;
}

// ---------- the one kernel: 2 rows per thread, W/V staged in smem ----------
__global__ void __launch_bounds__(256, 2)
rcpl_kernel(const float4* __restrict__ y,
            const float* __restrict__ Wg,
            const float* __restrict__ Vg,
            float4* __restrict__ out,
            int B)
{
    __shared__ float sWV[32];
    if (threadIdx.x < 32)
        sWV[threadIdx.x] = (threadIdx.x < 16) ? Wg[threadIdx.x]
                                              : Vg[threadIdx.x - 16];
    __syncthreads();
    const float* sW = sWV;
    const float* sV = sWV + 16;

    int tid = blockIdx.x * blockDim.x + threadIdx.x;
    int half = (B + 1) >> 1;
    if (tid >= half) return;

    int b0 = tid;
    int b1 = tid + half;

    // hot, branch-free compute for both rows in one basic block (ILP=2)
    bool r0 = false, r1 = false;
    float4 a0 = row_fast(y, sW, sV, b0, r0);
    float4 a1;
    bool have1 = b1 < B;
    if (have1) a1 = row_fast(y, sW, sV, b1, r1);

    // cold, rare fp64 pinv branches (recompute from y; bit-exact)
    if (r0) a0 = solve_slow(y, sW, sV, b0);
    if (have1 && r1) a1 = solve_slow(y, sW, sV, b1);

    out[b0] = a0;
    if (have1) out[b1] = a1;
}

extern "C" void kernel_launch(void* const* d_in, const int* in_sizes, int n_in,
                              void* d_out, int out_size)
{
    const float* y = (const float*)d_in[0];
    const float* W = (const float*)d_in[1];
    const float* V = (const float*)d_in[2];
    int B = in_sizes[0] / 8;   // y is [B, 8]

    int half = (B + 1) >> 1;
    int threads = 256;
    int blocks = (half + threads - 1) / threads;
    rcpl_kernel<<<blocks, threads>>>((const float4*)y, W, V, (float4*)d_out, B);
}

// round 13
// speedup vs baseline: 1.0904x; 1.0014x over previous
#include <cuda_runtime.h>

// Relativistic charged-particle Lagrangian dynamics — ONE graph node.
// R13 = R12 (ILP=2, smem-staged W/V) with non-amplified instruction trims:
//   - symmetric adjugate (10 computed entries, 6 mirrored)
//   - __frcp_rn + Newton instead of correctly-rounded div for 1/det
//   - symmetry-folded routing norms
// The kappa-amplified bits are untouched: bit-exact XLA H (tanh rational
// approx, cublas fma k-chains, (0.1*A_j)*A_i association, const-folded
// +eta), compensated 2x2 minors, double-single determinant. Routing at
// 4*RCOND to a cold fp64 adjugate/deflation path (no fp64 div/sqrt).

#define RCOND 4.7683716e-6f   /* 10 * 4 * eps(f32): jnp pinv default */

// ---------- XLA GPU f32 tanh ----------
__device__ __forceinline__ float xla_tanh(float x) {
    float ax = fabsf(x);
    float xc = fminf(fmaxf(x, -7.90531110763549805f), 7.90531110763549805f);
    float x2 = __fmul_rn(xc, xc);
    float np = -2.76076847742355e-16f;
    np = __fmaf_rn(np, x2, 2.00018790482477e-13f);
    np = __fmaf_rn(np, x2, -8.60467152213735e-11f);
    np = __fmaf_rn(np, x2, 5.12229709037114e-08f);
    np = __fmaf_rn(np, x2, 1.48572235717979e-05f);
    np = __fmaf_rn(np, x2, 6.37261928875436e-04f);
    np = __fmaf_rn(np, x2, 4.89352455891786e-03f);
    float num = __fmul_rn(xc, np);
    float dp = 1.19825839466702e-06f;
    dp = __fmaf_rn(dp, x2, 1.18534705686654e-04f);
    dp = __fmaf_rn(dp, x2, 2.26843463243900e-03f);
    dp = __fmaf_rn(dp, x2, 4.89352518554385e-03f);
    float r = __fdiv_rn(num, dp);
    return (ax < 0.0004f) ? x : r;
}

// ---------- double-single helpers ----------
__device__ __forceinline__ void two_sum(float a, float b, float& s, float& e) {
    s = a + b;
    float bb = s - a;
    e = (a - (s - bb)) + (b - bb);
}
__device__ __forceinline__ void two_prod(float a, float b, float& p, float& e) {
    p = a * b;
    e = fmaf(a, b, -p);
}
__device__ __forceinline__ float dif2(float p0, float p1, float q0, float q1) {
    float w = q0 * q1;
    float e = fmaf(q0, q1, -w);
    float r = fmaf(p0, p1, -w);
    return r - e;
}

// ---------- physics: J_uu (bit-exact vs reference) + force (compact) ----------
__device__ __forceinline__ void compute_mf(const float4* __restrict__ y,
                                           const float* sW, const float* sV,
                                           int b, float m[4][4], float force[4])
{
    const float eta[4] = {1.f, -1.f, -1.f, -1.f};
    float4 xv = y[2 * b];
    float4 uv = y[2 * b + 1];
    float x[4] = {xv.x, xv.y, xv.z, xv.w};
    float u[4] = {uv.x, uv.y, uv.z, uv.w};

    float A[4], dk[4];
#pragma unroll
    for (int i = 0; i < 4; i++) {
        float wx = __fmul_rn(sW[i*4+0], x[0]);
        wx = __fmaf_rn(sW[i*4+1], x[1], wx);
        wx = __fmaf_rn(sW[i*4+2], x[2], wx);
        wx = __fmaf_rn(sW[i*4+3], x[3], wx);
        float vx = __fmul_rn(sV[i*4+0], x[0]);
        vx = __fmaf_rn(sV[i*4+1], x[1], vx);
        vx = __fmaf_rn(sV[i*4+2], x[2], vx);
        vx = __fmaf_rn(sV[i*4+3], x[3], vx);
        float t = xla_tanh(wx);
        A[i]  = __fadd_rn(t, vx);
        dk[i] = __fsub_rn(1.0f, __fmul_rn(t, t));
    }

    // ---- J_uu: BIT-CRITICAL layout (matches reference autodiff graph) ----
    float oA[4];
#pragma unroll
    for (int j = 0; j < 4; j++)
        oA[j] = __fmul_rn(0.1f, A[j]);
#pragma unroll
    for (int i = 0; i < 4; i++) {
#pragma unroll
        for (int j = 0; j < 4; j++)
            m[i][j] = __fmul_rn(oA[j], A[i]);
        float xx2 = __fmul_rn(__fmul_rn(0.2f, x[i]), x[i]);
        m[i][i] = __fadd_rn(__fadd_rn(m[i][i], xx2), eta[i]);
    }

    // ---- force: compact algebra (rounding not kappa-amplified) ----
    float G[4][4];
#pragma unroll
    for (int k = 0; k < 4; k++)
#pragma unroll
        for (int j = 0; j < 4; j++)
            G[j][k] = fmaf(sW[k*4+j], dk[k], sV[k*4+j]);

    float s = u[0]*A[0] + u[1]*A[1] + u[2]*A[2] + u[3]*A[3];
    float tbs = 0.1f * s;

    float g[4], ge[4], h[4];
#pragma unroll
    for (int j = 0; j < 4; j++) {
        g[j]  = G[j][0]*u[0] + G[j][1]*u[1] + G[j][2]*u[2] + G[j][3]*u[3];
        ge[j] = G[j][0]*u[0] - G[j][1]*u[1] - G[j][2]*u[2] - G[j][3]*u[3];
        h[j]  = G[0][j]*u[0] + G[1][j]*u[1] + G[2][j]*u[2] + G[3][j]*u[3];
    }
    float p = h[0]*u[0] + h[1]*u[1] + h[2]*u[2] + h[3]*u[3];

#pragma unroll
    for (int j = 0; j < 4; j++) {
        force[j] = -0.2f * x[j] * u[j] * u[j]
                 + 0.5f * ge[j] + tbs * g[j]
                 - 0.5f * eta[j] * h[j] - tbs * h[j]
                 - 0.1f * p * A[j];
    }
}

// ---------- cold path: bit-exact recompute + fp64 pinv (no fp64 div/sqrt) ----
__device__ __noinline__ float4 solve_slow(const float4* __restrict__ y,
                                          const float* sW, const float* sV, int b)
{
    float mm[4][4], ff[4];
    compute_mf(y, sW, sV, b, mm, ff);

    double M[4][4], F[4];
#pragma unroll
    for (int i = 0; i < 4; i++) {
        F[i] = (double)ff[i];
#pragma unroll
        for (int j = 0; j < 4; j++)
            M[i][j] = (double)mm[i][j];
    }

    double s0 = M[0][0]*M[1][1] - M[1][0]*M[0][1];
    double s1 = M[0][0]*M[1][2] - M[1][0]*M[0][2];
    double s2 = M[0][0]*M[1][3] - M[1][0]*M[0][3];
    double s3 = M[0][1]*M[1][2] - M[1][1]*M[0][2];
    double s4 = M[0][1]*M[1][3] - M[1][1]*M[0][3];
    double s5 = M[0][2]*M[1][3] - M[1][2]*M[0][3];
    double c5 = M[2][2]*M[3][3] - M[3][2]*M[2][3];
    double c4 = M[2][1]*M[3][3] - M[3][1]*M[2][3];
    double c3 = M[2][1]*M[3][2] - M[3][1]*M[2][2];
    double c2 = M[2][0]*M[3][3] - M[3][0]*M[2][3];
    double c1 = M[2][0]*M[3][2] - M[3][0]*M[2][2];
    double c0 = M[2][0]*M[3][1] - M[3][0]*M[2][1];

    double det = s0*c5 - s1*c4 + s2*c3 + s3*c2 - s4*c1 + s5*c0;

    double adj[4][4];
    adj[0][0] =  M[1][1]*c5 - M[1][2]*c4 + M[1][3]*c3;
    adj[0][1] = -M[0][1]*c5 + M[0][2]*c4 - M[0][3]*c3;
    adj[0][2] =  M[3][1]*s5 - M[3][2]*s4 + M[3][3]*s3;
    adj[0][3] = -M[2][1]*s5 + M[2][2]*s4 - M[2][3]*s3;
    adj[1][0] = -M[1][0]*c5 + M[1][2]*c2 - M[1][3]*c1;
    adj[1][1] =  M[0][0]*c5 - M[0][2]*c2 + M[0][3]*c1;
    adj[1][2] = -M[3][0]*s5 + M[3][2]*s2 - M[3][3]*s1;
    adj[1][3] =  M[2][0]*s5 - M[2][2]*s2 + M[2][3]*s1;
    adj[2][0] =  M[1][0]*c4 - M[1][1]*c2 + M[1][3]*c0;
    adj[2][1] = -M[0][0]*c4 + M[0][1]*c2 - M[0][3]*c0;
    adj[2][2] =  M[3][0]*s4 - M[3][1]*s2 + M[3][3]*s0;
    adj[2][3] = -M[2][0]*s4 + M[2][1]*s2 - M[2][3]*s0;
    adj[3][0] = -M[1][0]*c3 + M[1][1]*c1 - M[1][2]*c0;
    adj[3][1] =  M[0][0]*c3 - M[0][1]*c1 + M[0][2]*c0;
    adj[3][2] = -M[3][0]*s3 + M[3][1]*s1 - M[3][2]*s0;
    adj[3][3] =  M[2][0]*s3 - M[2][1]*s1 + M[2][2]*s0;

    double rdet = (double)__frcp_rn((float)det);
    rdet = rdet * (2.0 - det * rdet);
    rdet = rdet * (2.0 - det * rdet);

    double acc[4];
#pragma unroll
    for (int j = 0; j < 4; j++)
        acc[j] = (F[0]*adj[0][j] + F[1]*adj[1][j]
                + F[2]*adj[2][j] + F[3]*adj[3][j]) * rdet;

    // null direction: dominant adjugate column + one refinement multiply
    double cn[4];
#pragma unroll
    for (int c = 0; c < 4; c++)
        cn[c] = adj[0][c]*adj[0][c] + adj[1][c]*adj[1][c]
              + adj[2][c]*adj[2][c] + adj[3][c]*adj[3][c];
    int cbest = 0;
    if (cn[1] > cn[cbest]) cbest = 1;
    if (cn[2] > cn[cbest]) cbest = 2;
    if (cn[3] > cn[cbest]) cbest = 3;
    double v[4] = {adj[0][cbest], adj[1][cbest], adj[2][cbest], adj[3][cbest]};
    double v2[4];
#pragma unroll
    for (int i = 0; i < 4; i++)
        v2[i] = adj[i][0]*v[0] + adj[i][1]*v[1] + adj[i][2]*v[2] + adj[i][3]*v[3];

    double Mv[4];
#pragma unroll
    for (int i = 0; i < 4; i++)
        Mv[i] = M[i][0]*v2[0] + M[i][1]*v2[1] + M[i][2]*v2[2] + M[i][3]*v2[3];
    double num = v2[0]*Mv[0] + v2[1]*Mv[1] + v2[2]*Mv[2] + v2[3]*Mv[3];
    double den = v2[0]*v2[0] + v2[1]*v2[1] + v2[2]*v2[2] + v2[3]*v2[3];

    // sigma_max^2 via power iteration on M^2 (compare in squares, no sqrt)
    double tn[4];
#pragma unroll
    for (int c = 0; c < 4; c++)
        tn[c] = M[0][c]*M[0][c] + M[1][c]*M[1][c]
              + M[2][c]*M[2][c] + M[3][c]*M[3][c];
    int tbest = 0;
    if (tn[1] > tn[tbest]) tbest = 1;
    if (tn[2] > tn[tbest]) tbest = 2;
    if (tn[3] > tn[tbest]) tbest = 3;
    double t[4] = {M[0][tbest], M[1][tbest], M[2][tbest], M[3][tbest]};
#pragma unroll
    for (int it = 0; it < 6; it++) {
        double tt0 = M[0][0]*t[0] + M[0][1]*t[1] + M[0][2]*t[2] + M[0][3]*t[3];
        double tt1 = M[1][0]*t[0] + M[1][1]*t[1] + M[1][2]*t[2] + M[1][3]*t[3];
        double tt2 = M[2][0]*t[0] + M[2][1]*t[1] + M[2][2]*t[2] + M[2][3]*t[3];
        double tt3 = M[3][0]*t[0] + M[3][1]*t[1] + M[3][2]*t[2] + M[3][3]*t[3];
        t[0] = tt0; t[1] = tt1; t[2] = tt2; t[3] = tt3;
    }
    double z0 = M[0][0]*t[0] + M[0][1]*t[1] + M[0][2]*t[2] + M[0][3]*t[3];
    double z1 = M[1][0]*t[0] + M[1][1]*t[1] + M[1][2]*t[2] + M[1][3]*t[3];
    double z2 = M[2][0]*t[0] + M[2][1]*t[1] + M[2][2]*t[2] + M[2][3]*t[3];
    double z3 = M[3][0]*t[0] + M[3][1]*t[1] + M[3][2]*t[2] + M[3][3]*t[3];
    double zz = z0*z0 + z1*z1 + z2*z2 + z3*z3;
    double tt = t[0]*t[0] + t[1]*t[1] + t[2]*t[2] + t[3]*t[3];
    double R2 = (double)RCOND * (double)RCOND;
    bool keep = (num*num)*tt > R2*zz*(den*den);

    if (!keep) {
        double rden = (double)__frcp_rn((float)den);
        rden = rden * (2.0 - den * rden);
        rden = rden * (2.0 - den * rden);
        double proj = (v2[0]*acc[0] + v2[1]*acc[1]
                     + v2[2]*acc[2] + v2[3]*acc[3]) * rden;
#pragma unroll
        for (int j = 0; j < 4; j++)
            acc[j] -= proj * v2[j];
    }

    return make_float4((float)acc[0], (float)acc[1], (float)acc[2], (float)acc[3]);
}

// ---------- hot row: branch-free fast solve + routing flag ----------
__device__ __forceinline__ float4 row_fast(const float4* __restrict__ y,
                                           const float* sW, const float* sV,
                                           int b, bool& routed)
{
    float m[4][4], f[4];
    compute_mf(y, sW, sV, b, m, f);

    // compensated 2x2 minors — BIT-CRITICAL (feed the determinant)
    float s0 = dif2(m[0][0], m[1][1], m[1][0], m[0][1]);
    float s1 = dif2(m[0][0], m[1][2], m[1][0], m[0][2]);
    float s2 = dif2(m[0][0], m[1][3], m[1][0], m[0][3]);
    float s3 = dif2(m[0][1], m[1][2], m[1][1], m[0][2]);
    float s4 = dif2(m[0][1], m[1][3], m[1][1], m[0][3]);
    float s5 = dif2(m[0][2], m[1][3], m[1][2], m[0][3]);

    float c5 = dif2(m[2][2], m[3][3], m[3][2], m[2][3]);
    float c4 = dif2(m[2][1], m[3][3], m[3][1], m[2][3]);
    float c3 = dif2(m[2][1], m[3][2], m[3][1], m[2][2]);
    float c2 = dif2(m[2][0], m[3][3], m[3][0], m[2][3]);
    float c1 = dif2(m[2][0], m[3][2], m[3][0], m[2][2]);
    float c0 = dif2(m[2][0], m[3][1], m[3][0], m[2][1]);

    // determinant in double-single — BIT-CRITICAL
    float hi, lo, p, e, t;
    two_prod(s0, c5, hi, lo);
    two_prod(-s1, c4, p, e); two_sum(hi, p, hi, t); lo += t + e;
    two_prod(s2, c3, p, e);  two_sum(hi, p, hi, t); lo += t + e;
    two_prod(s3, c2, p, e);  two_sum(hi, p, hi, t); lo += t + e;
    two_prod(-s4, c1, p, e); two_sum(hi, p, hi, t); lo += t + e;
    two_prod(s5, c0, p, e);  two_sum(hi, p, hi, t); lo += t + e;

    // adjugate: m is symmetric to ulps, so compute the 10 upper entries and
    // mirror the rest (adj enters acc un-amplified; ~1 ulp effect).
    float adj[4][4];
    adj[0][0] =  m[1][1]*c5 - m[1][2]*c4 + m[1][3]*c3;
    adj[0][1] = -m[0][1]*c5 + m[0][2]*c4 - m[0][3]*c3;
    adj[0][2] =  m[3][1]*s5 - m[3][2]*s4 + m[3][3]*s3;
    adj[0][3] = -m[2][1]*s5 + m[2][2]*s4 - m[2][3]*s3;
    adj[1][1] =  m[0][0]*c5 - m[0][2]*c2 + m[0][3]*c1;
    adj[1][2] = -m[3][0]*s5 + m[3][2]*s2 - m[3][3]*s1;
    adj[1][3] =  m[2][0]*s5 - m[2][2]*s2 + m[2][3]*s1;
    adj[2][2] =  m[3][0]*s4 - m[3][1]*s2 + m[3][3]*s0;
    adj[2][3] = -m[2][0]*s4 + m[2][1]*s2 - m[2][3]*s0;
    adj[3][3] =  m[2][0]*s3 - m[2][1]*s1 + m[2][2]*s0;
    adj[1][0] = adj[0][1];
    adj[2][0] = adj[0][2];
    adj[3][0] = adj[0][3];
    adj[2][1] = adj[1][2];
    adj[3][1] = adj[1][3];
    adj[3][2] = adj[2][3];

    // routing norms (threshold only): fold symmetry, diag + 2*upper
    float sF2 = m[0][0]*m[0][0] + m[1][1]*m[1][1]
              + m[2][2]*m[2][2] + m[3][3]*m[3][3];
    float oF2 = m[0][1]*m[0][1] + m[0][2]*m[0][2] + m[0][3]*m[0][3]
              + m[1][2]*m[1][2] + m[1][3]*m[1][3] + m[2][3]*m[2][3];
    sF2 = fmaf(2.0f, oF2, sF2);

    float sAdj2 = adj[0][0]*adj[0][0] + adj[1][1]*adj[1][1]
                + adj[2][2]*adj[2][2] + adj[3][3]*adj[3][3];
    float oAdj2 = adj[0][1]*adj[0][1] + adj[0][2]*adj[0][2] + adj[0][3]*adj[0][3]
                + adj[1][2]*adj[1][2] + adj[1][3]*adj[1][3] + adj[2][3]*adj[2][3];
    sAdj2 = fmaf(2.0f, oAdj2, sAdj2);

    float det1 = hi + lo;
    const float CR = 4.0f * RCOND;
    routed = det1 * det1 < (CR * CR) * sF2 * sAdj2;

    // 1/(hi+lo): frcp seed + 1 Newton + lo fixup (un-amplified; ~1 ulp)
    float inv = __frcp_rn(hi);
    float err = fmaf(-hi, inv, 1.0f);
    inv = fmaf(inv, err, inv);
    inv = fmaf(-lo, inv * inv, inv);

    float4 res;
    res.x = (f[0]*adj[0][0] + f[1]*adj[1][0] + f[2]*adj[2][0] + f[3]*adj[3][0]) * inv;
    res.y = (f[0]*adj[0][1] + f[1]*adj[1][1] + f[2]*adj[2][1] + f[3]*adj[3][1]) * inv;
    res.z = (f[0]*adj[0][2] + f[1]*adj[1][2] + f[2]*adj[2][2] + f[3]*adj[3][2]) * inv;
    res.w = (f[0]*adj[0][3] + f[1]*adj[1][3] + f[2]*adj[2][3] + f[3]*adj[3][3]) * inv;
    return res;
}

// ---------- the one kernel: 2 rows per thread, W/V staged in smem ----------
__global__ void __launch_bounds__(256, 2)
rcpl_kernel(const float4* __restrict__ y,
            const float* __restrict__ Wg,
            const float* __restrict__ Vg,
            float4* __restrict__ out,
            int B)
{
    __shared__ float sWV[32];
    if (threadIdx.x < 32)
        sWV[threadIdx.x] = (threadIdx.x < 16) ? Wg[threadIdx.x]
                                              : Vg[threadIdx.x - 16];
    __syncthreads();
    const float* sW = sWV;
    const float* sV = sWV + 16;

    int tid = blockIdx.x * blockDim.x + threadIdx.x;
    int half = (B + 1) >> 1;
    if (tid >= half) return;

    int b0 = tid;
    int b1 = tid + half;

    // hot, branch-free compute for both rows in one basic block (ILP=2)
    bool r0 = false, r1 = false;
    float4 a0 = row_fast(y, sW, sV, b0, r0);
    float4 a1;
    bool have1 = b1 < B;
    if (have1) a1 = row_fast(y, sW, sV, b1, r1);

    // cold, rare fp64 pinv branches (recompute from y; bit-exact)
    if (r0) a0 = solve_slow(y, sW, sV, b0);
    if (have1 && r1) a1 = solve_slow(y, sW, sV, b1);

    out[b0] = a0;
    if (have1) out[b1] = a1;
}

extern "C" void kernel_launch(void* const* d_in, const int* in_sizes, int n_in,
                              void* d_out, int out_size)
{
    const float* y = (const float*)d_in[0];
    const float* W = (const float*)d_in[1];
    const float* V = (const float*)d_in[2];
    int B = in_sizes[0] / 8;   // y is [B, 8]

    int half = (B + 1) >> 1;
    int threads = 256;
    int blocks = (half + threads - 1) / threads;
    rcpl_kernel<<<blocks, threads>>>((const float4*)y, W, V, (float4*)d_out, B);
}